// round 6
// baseline (speedup 1.0000x reference)
#include <cuda_runtime.h>
#include <cuda_bf16.h>
#include <cstdint>
#include <math.h>

// ============================================================
// DocAttention on GB300 (sm_103 family-safe: mma.sync bf16).
//   logits[b,x] = Q[b,x]·(Σ_a K[b,a]) − Q[b,x]·K[b,x]
//   Q = (cls@Wq + bq)*m, K = (cls@Wk + bk)*m
//   out = softmax(logits + (1−m)·−1e5)
// Masked rows (m=0) are compacted out of the GEMM entirely.
// ============================================================

__device__ __forceinline__ uint32_t smem_u32(const void* p) {
    uint32_t a;
    asm("{ .reg .u64 t; cvta.to.shared.u64 t, %1; cvt.u32.u64 %0, t; }"
        : "=r"(a) : "l"(p));
    return a;
}

// ---------------- scratch (device globals; no allocation) ----------------
__device__ __align__(16) __nv_bfloat16 g_A[1024 * 1024];    // cls bf16 [m][k]
__device__ __align__(16) __nv_bfloat16 g_W[2 * 1024 * 1024];// Wq|Wk bf16, native [d][n]
__device__ float g_qk[1024 * 2048];                          // Q | K at ORIGINAL rows
__device__ float g_part[1024 * 8];                           // partial logits
__device__ int   g_rowlist[1024];                            // active row indices
__device__ int   g_rowcnt;                                   // number of active rows
__device__ int   g_ctr;                                      // epi last-block counter

// ---------------- converts + row compaction ----------------
// blocks [0,1024): cls row f32 -> bf16
// blocks [1024,3072): W elementwise f32 -> bf16 (native layout)
// block 3072: warp-ballot compaction of mask -> g_rowlist/g_rowcnt
__global__ __launch_bounds__(256) void convert_all(const float* __restrict__ enc,
                                                   const float* __restrict__ wq,
                                                   const float* __restrict__ wk,
                                                   const int*   __restrict__ mask) {
    const int blk = blockIdx.x;
    const int tid = threadIdx.x;

    if (blk < 1024) {
        const int row = blk;
        const float4 v = reinterpret_cast<const float4*>(enc + (size_t)row * 131072)[tid];
        __nv_bfloat16 h[4];
        h[0] = __float2bfloat16(v.x);
        h[1] = __float2bfloat16(v.y);
        h[2] = __float2bfloat16(v.z);
        h[3] = __float2bfloat16(v.w);
        *reinterpret_cast<uint2*>(g_A + (size_t)row * 1024 + tid * 4) =
            *reinterpret_cast<uint2*>(h);
        return;
    }
    if (blk < 3072) {
        const int idx = blk - 1024;              // 0..2047 (row of 1024 floats)
        const float* __restrict__ src = (idx < 1024)
            ? (wq + (size_t)idx * 1024)
            : (wk + (size_t)(idx - 1024) * 1024);
        const float4 v = reinterpret_cast<const float4*>(src)[tid];
        __nv_bfloat16 h[4];
        h[0] = __float2bfloat16(v.x);
        h[1] = __float2bfloat16(v.y);
        h[2] = __float2bfloat16(v.z);
        h[3] = __float2bfloat16(v.w);
        *reinterpret_cast<uint2*>(g_W + (size_t)idx * 1024 + tid * 4) =
            *reinterpret_cast<uint2*>(h);
        return;
    }
    // compaction: warp 0 only
    if (tid < 32) {
        int prev = 0;
        #pragma unroll
        for (int it = 0; it < 32; it++) {
            const int idx = it * 32 + tid;
            const bool v = (mask[idx] != 0);
            const unsigned ball = __ballot_sync(0xFFFFFFFFu, v);
            if (v) {
                const int pos = prev + __popc(ball & ((1u << tid) - 1u));
                g_rowlist[pos] = idx;
            }
            prev += __popc(ball);
        }
        if (tid == 0) g_rowcnt = prev;
    }
}

// ---------------- mma.sync GEMM (compacted rows) ----------------
// CTA: 128x128 tile, 256 threads = 8 warps 2(M) x 4(N); warp tile 64x32.
// A smem: [128 m][128B k], swizzled. B smem: [64 k][256B n], swizzled,
// consumed via ldmatrix.trans (W kept in native [d][n] layout).
#define BK 64
#define STAGE_BYTES 32768
#define NSTAGE 4

__global__ __launch_bounds__(256, 1)
void qk_mma_sync(const float* __restrict__ bq,
                 const float* __restrict__ bk) {
    const int cnt = g_rowcnt;
    const int mBase = blockIdx.y * 128;
    if (mBase >= cnt) return;

    extern __shared__ __align__(1024) char smem[];
    __shared__ int rlTile[128];
    const uint32_t base = smem_u32(smem);
    const int tid = threadIdx.x;
    const int warp = tid >> 5, lane = tid & 31;
    const int bx = blockIdx.x;           // 0..15
    const int z = (bx >> 3);             // 0 = Q (wq), 1 = K (wk)
    const int colBase = (bx & 7) * 128;  // within 0..1023
    const int mw = (warp & 1) * 64;
    const int nw = (warp >> 1) * 32;

    if (tid < 128)
        rlTile[tid] = (mBase + tid < cnt) ? g_rowlist[mBase + tid] : 0;
    __syncthreads();

    float c[4][4][4];
    #pragma unroll
    for (int i = 0; i < 4; i++)
        #pragma unroll
        for (int j = 0; j < 4; j++)
            #pragma unroll
            for (int r = 0; r < 4; r++) c[i][j][r] = 0.f;

    const __nv_bfloat16* __restrict__ Wbase =
        g_W + (size_t)z * 1048576 + colBase;

    auto issue = [&](int kb) {
        const int stage = kb & (NSTAGE - 1);
        const uint32_t sA = base + (uint32_t)stage * STAGE_BYTES;
        const uint32_t sB = sA + 16384;
        const int k0 = kb * BK;
        // A: 128 rows x 8 chunks(16B)
        #pragma unroll
        for (int i = 0; i < 4; i++) {
            const int idx = i * 256 + tid;
            const int row = idx >> 3;
            const int ch = idx & 7;
            const __nv_bfloat16* gA =
                g_A + (size_t)rlTile[row] * 1024 + k0 + ch * 8;
            asm volatile("cp.async.cg.shared.global [%0], [%1], 16;"
                :: "r"(sA + (uint32_t)(row * 128 + ((ch ^ (row & 7)) << 4))),
                   "l"(gA));
        }
        // B: 64 k-rows x 16 chunks(16B) of native [d][n]
        #pragma unroll
        for (int i = 0; i < 4; i++) {
            const int idx = i * 256 + tid;
            const int row = idx >> 4;            // k within chunk
            const int ch = idx & 15;             // n chunk
            const __nv_bfloat16* gB =
                Wbase + (size_t)(k0 + row) * 1024 + ch * 8;
            asm volatile("cp.async.cg.shared.global [%0], [%1], 16;"
                :: "r"(sB + (uint32_t)(row * 256 + ((ch ^ (row & 7)) << 4))),
                   "l"(gB));
        }
        asm volatile("cp.async.commit_group;");
    };

    const int lj = lane >> 3;
    const int li = lane & 7;
    auto compute = [&](int stage) {
        const uint32_t sA = base + (uint32_t)stage * STAGE_BYTES;
        const uint32_t sB = sA + 16384;
        #pragma unroll
        for (int kc = 0; kc < BK / 16; kc++) {
            uint32_t a[4][4];
            #pragma unroll
            for (int mt = 0; mt < 4; mt++) {
                const int row = mw + mt * 16 + ((lj & 1) << 3) + li;
                const int ch = kc * 2 + (lj >> 1);
                const uint32_t addr =
                    sA + (uint32_t)(row * 128 + ((ch ^ (row & 7)) << 4));
                asm volatile("ldmatrix.sync.aligned.m8n8.x4.shared.b16 "
                             "{%0,%1,%2,%3}, [%4];"
                             : "=r"(a[mt][0]), "=r"(a[mt][1]),
                               "=r"(a[mt][2]), "=r"(a[mt][3])
                             : "r"(addr));
            }
            uint32_t b[2][4];
            #pragma unroll
            for (int nh = 0; nh < 2; nh++) {
                // trans load from [k][n] tile: lanes address k-rows
                const int krow = kc * 16 + ((lj & 1) << 3) + li;
                const int nchunk = (nw >> 3) + nh * 2 + (lj >> 1);
                const uint32_t addr =
                    sB + (uint32_t)(krow * 256 + ((nchunk ^ (krow & 7)) << 4));
                asm volatile("ldmatrix.sync.aligned.m8n8.x4.trans.shared.b16 "
                             "{%0,%1,%2,%3}, [%4];"
                             : "=r"(b[nh][0]), "=r"(b[nh][1]),
                               "=r"(b[nh][2]), "=r"(b[nh][3])
                             : "r"(addr));
            }
            #pragma unroll
            for (int mt = 0; mt < 4; mt++)
                #pragma unroll
                for (int nt = 0; nt < 4; nt++) {
                    const uint32_t b0 = b[nt >> 1][(nt & 1) * 2 + 0];
                    const uint32_t b1 = b[nt >> 1][(nt & 1) * 2 + 1];
                    asm volatile(
                        "mma.sync.aligned.m16n8k16.row.col.f32.bf16.bf16.f32 "
                        "{%0,%1,%2,%3}, {%4,%5,%6,%7}, {%8,%9}, {%0,%1,%2,%3};"
                        : "+f"(c[mt][nt][0]), "+f"(c[mt][nt][1]),
                          "+f"(c[mt][nt][2]), "+f"(c[mt][nt][3])
                        : "r"(a[mt][0]), "r"(a[mt][1]),
                          "r"(a[mt][2]), "r"(a[mt][3]),
                          "r"(b0), "r"(b1));
                }
        }
    };

    issue(0); issue(1); issue(2);
    for (int kb = 0; kb < 16; kb++) {
        if (kb <= 13)      asm volatile("cp.async.wait_group 2;");
        else if (kb == 14) asm volatile("cp.async.wait_group 1;");
        else               asm volatile("cp.async.wait_group 0;");
        __syncthreads();
        if (kb + 3 < 16) issue(kb + 3);
        compute(kb & (NSTAGE - 1));
    }

    // epilogue: bias, scatter to original rows (active rows all have m=1)
    const float* __restrict__ bias = z ? bk : bq;
    #pragma unroll
    for (int mt = 0; mt < 4; mt++) {
        #pragma unroll
        for (int half = 0; half < 2; half++) {
            const int compact = mBase + mw + mt * 16 + (lane >> 2) + half * 8;
            if (compact >= cnt) continue;
            const int orig = rlTile[compact - mBase];
            #pragma unroll
            for (int nt = 0; nt < 4; nt++) {
                const int colL = colBase + nw + nt * 8 + (lane & 3) * 2;
                float2 v;
                v.x = c[mt][nt][half * 2 + 0] + bias[colL + 0];
                v.y = c[mt][nt][half * 2 + 1] + bias[colL + 1];
                *reinterpret_cast<float2*>(
                    g_qk + (size_t)orig * 2048 + z * 1024 + colL) = v;
            }
        }
    }
}

// ---------------- epi: partials + last-block softmax ----------------
// grid (8, 32): blockIdx.x = 128-dim slice, blockIdx.y = batch. 256 threads.
__global__ __launch_bounds__(256) void epi(const int* __restrict__ mask,
                                           float* __restrict__ out) {
    const int ds = blockIdx.x;
    const int b  = blockIdx.y;
    const int tid = threadIdx.x, warp = tid >> 5, lane = tid & 31;
    __shared__ float ks[128];
    __shared__ float sm_m[32];
    __shared__ int isLast;

    const float* __restrict__ base = g_qk + (size_t)b * 32 * 2048;
    const int d0 = ds * 128;

    if (tid < 32) sm_m[tid] = (float)mask[b * 32 + tid];
    __syncthreads();

    if (tid < 128) {
        float s = 0.f;
        #pragma unroll
        for (int a = 0; a < 32; a++)
            s += sm_m[a] * base[a * 2048 + 1024 + d0 + tid];
        ks[tid] = s;
    }
    __syncthreads();

    #pragma unroll
    for (int xi = 0; xi < 4; xi++) {
        const int x = warp + xi * 8;
        const float mx_ = sm_m[x];
        const float* __restrict__ q = base + (size_t)x * 2048 + d0;
        const float* __restrict__ k = q + 1024;
        const int d = lane * 4;
        const float4 qv = *reinterpret_cast<const float4*>(q + d);
        const float4 kv = *reinterpret_cast<const float4*>(k + d);
        const float4 sv = *reinterpret_cast<const float4*>(ks + d);
        float acc = qv.x * (sv.x - kv.x);
        acc = fmaf(qv.y, sv.y - kv.y, acc);
        acc = fmaf(qv.z, sv.z - kv.z, acc);
        acc = fmaf(qv.w, sv.w - kv.w, acc);
        #pragma unroll
        for (int o = 16; o > 0; o >>= 1)
            acc += __shfl_xor_sync(0xFFFFFFFFu, acc, o);
        if (lane == 0)
            g_part[(b * 32 + x) * 8 + ds] = (mx_ != 0.f) ? acc : 0.f;
    }

    // last block of the 256 finishes the job
    __syncthreads();
    if (tid == 0) {
        __threadfence();
        isLast = (atomicAdd(&g_ctr, 1) == 255);
    }
    __syncthreads();
    if (!isLast) return;
    if (tid == 0) g_ctr = 0;           // reset for next graph replay
    __threadfence();

    #pragma unroll
    for (int p = 0; p < 4; p++) {
        const int b2 = p * 8 + warp;
        float s = 0.f;
        #pragma unroll
        for (int d = 0; d < 8; d++)
            s += g_part[(b2 * 32 + lane) * 8 + d];
        const float m = (float)mask[b2 * 32 + lane];
        float v = (m != 0.f) ? s : -100000.0f;
        float mx = v;
        #pragma unroll
        for (int o = 16; o > 0; o >>= 1)
            mx = fmaxf(mx, __shfl_xor_sync(0xFFFFFFFFu, mx, o));
        const float e = expf(v - mx);
        float sum = e;
        #pragma unroll
        for (int o = 16; o > 0; o >>= 1)
            sum += __shfl_xor_sync(0xFFFFFFFFu, sum, o);
        out[b2 * 32 + lane] = e / sum;
    }
}

extern "C" void kernel_launch(void* const* d_in, const int* in_sizes, int n_in,
                              void* d_out, int out_size) {
    const float* enc  = (const float*)d_in[0];   // (32,32,128,1024) f32
    const int*   mask = (const int*)  d_in[1];   // (32,32) int32
    const float* wq   = (const float*)d_in[2];   // (1024,16,64) f32
    const float* bq   = (const float*)d_in[3];   // (16,64)
    const float* wk   = (const float*)d_in[4];
    const float* bk   = (const float*)d_in[5];
    float* out = (float*)d_out;                  // (32,32) f32

    cudaFuncSetAttribute(qk_mma_sync,
                         cudaFuncAttributeMaxDynamicSharedMemorySize,
                         NSTAGE * STAGE_BYTES);

    convert_all<<<3073, 256>>>(enc, wq, wk, mask);
    qk_mma_sync<<<dim3(16, 8), 256, NSTAGE * STAGE_BYTES>>>(bq, bk);
    epi<<<dim3(8, 32), 256>>>(mask, out);
}

// round 7
// speedup vs baseline: 1.0640x; 1.0640x over previous
#include <cuda_runtime.h>
#include <cuda_bf16.h>
#include <cstdint>
#include <math.h>

// ============================================================
// DocAttention on GB300 (sm_103 family-safe: mma.sync bf16).
//   logits[b,x] = Q[b,x]·(Σ_a K[b,a]) − Q[b,x]·K[b,x]
//   Q = (cls@Wq + bq)*m, K = (cls@Wk + bk)*m
//   out = softmax(logits + (1−m)·−1e5)
// Masked rows compacted out of the GEMM; 64-row tiles so the
// compacted grid still fills the machine.
// ============================================================

__device__ __forceinline__ uint32_t smem_u32(const void* p) {
    uint32_t a;
    asm("{ .reg .u64 t; cvta.to.shared.u64 t, %1; cvt.u32.u64 %0, t; }"
        : "=r"(a) : "l"(p));
    return a;
}

// ---------------- scratch (device globals; no allocation) ----------------
__device__ __align__(16) __nv_bfloat16 g_A[1024 * 1024];     // cls bf16 [m][k]
__device__ __align__(16) __nv_bfloat16 g_W[2 * 1024 * 1024]; // Wq|Wk bf16 native [d][n]
__device__ float g_qk[1024 * 2048];                           // Q | K at ORIGINAL rows
__device__ float g_part[1024 * 8];                            // partial logits
__device__ int   g_rowlist[1024];
__device__ int   g_rowcnt;
__device__ int   g_ctr;

// ---------------- converts + row compaction (bandwidth-shaped) ----------------
// blocks [0,256): cls, 4 rows/block, 64B/thread
// blocks [256,512): W stream, 128B/thread
// block 0 warp 0 additionally does mask compaction
__global__ __launch_bounds__(256) void convert_all(const float* __restrict__ enc,
                                                   const float* __restrict__ wq,
                                                   const float* __restrict__ wk,
                                                   const int*   __restrict__ mask) {
    const int blk = blockIdx.x;
    const int tid = threadIdx.x;

    if (blk < 256) {
        // cls: row = blk*4 + tid/64; 64 threads per row, 16 floats each
        const int row = blk * 4 + (tid >> 6);
        const int c16 = (tid & 63) * 16;                  // float offset in row
        const float4* __restrict__ src =
            reinterpret_cast<const float4*>(enc + (size_t)row * 131072 + c16);
        float4 v0 = src[0], v1 = src[1], v2 = src[2], v3 = src[3];
        __nv_bfloat16 h[16];
        h[0]=__float2bfloat16(v0.x); h[1]=__float2bfloat16(v0.y);
        h[2]=__float2bfloat16(v0.z); h[3]=__float2bfloat16(v0.w);
        h[4]=__float2bfloat16(v1.x); h[5]=__float2bfloat16(v1.y);
        h[6]=__float2bfloat16(v1.z); h[7]=__float2bfloat16(v1.w);
        h[8]=__float2bfloat16(v2.x); h[9]=__float2bfloat16(v2.y);
        h[10]=__float2bfloat16(v2.z); h[11]=__float2bfloat16(v2.w);
        h[12]=__float2bfloat16(v3.x); h[13]=__float2bfloat16(v3.y);
        h[14]=__float2bfloat16(v3.z); h[15]=__float2bfloat16(v3.w);
        uint4* dst = reinterpret_cast<uint4*>(g_A + (size_t)row * 1024 + c16);
        dst[0] = reinterpret_cast<uint4*>(h)[0];
        dst[1] = reinterpret_cast<uint4*>(h)[1];

        if (blk == 0 && tid < 32) {
            int prev = 0;
            #pragma unroll
            for (int it = 0; it < 32; it++) {
                const int idx = it * 32 + tid;
                const bool v = (mask[idx] != 0);
                const unsigned ball = __ballot_sync(0xFFFFFFFFu, v);
                if (v) g_rowlist[prev + __popc(ball & ((1u << tid) - 1u))] = idx;
                prev += __popc(ball);
            }
            if (tid == 0) g_rowcnt = prev;
        }
        return;
    }

    // W stream: widx 0..255, each block converts 8192 floats
    const int widx = blk - 256;
    const size_t off = (size_t)(widx & 127) * 8192 + tid * 32;
    const float4* __restrict__ src = reinterpret_cast<const float4*>(
        ((widx < 128) ? wq : wk) + off);
    float4 v[8];
    #pragma unroll
    for (int i = 0; i < 8; i++) v[i] = src[i];
    __nv_bfloat16 h[32];
    #pragma unroll
    for (int i = 0; i < 8; i++) {
        h[i*4+0] = __float2bfloat16(v[i].x);
        h[i*4+1] = __float2bfloat16(v[i].y);
        h[i*4+2] = __float2bfloat16(v[i].z);
        h[i*4+3] = __float2bfloat16(v[i].w);
    }
    uint4* dst = reinterpret_cast<uint4*>(g_W + (size_t)widx * 8192 + tid * 32);
    #pragma unroll
    for (int i = 0; i < 4; i++) dst[i] = reinterpret_cast<uint4*>(h)[i];
}

// ---------------- mma.sync GEMM (compacted rows, 64x128 tiles) ----------------
// CTA: 64x128 tile, 256 threads = 8 warps 2(M) x 4(N); warp tile 32x32.
// A smem: [64 m][128B k] swizzled; B smem: [64 k][256B n] swizzled (ldmatrix.trans).
#define BK 64
#define A_BYTES 8192
#define B_BYTES 16384
#define STAGE_BYTES (A_BYTES + B_BYTES)
#define NSTAGE 4

__global__ __launch_bounds__(256, 1)
void qk_mma_sync(const float* __restrict__ bq,
                 const float* __restrict__ bk) {
    const int cnt = g_rowcnt;
    const int mBase = blockIdx.y * 64;
    if (mBase >= cnt) return;

    extern __shared__ __align__(1024) char smem[];
    __shared__ int rlTile[64];
    const uint32_t base = smem_u32(smem);
    const int tid = threadIdx.x;
    const int warp = tid >> 5, lane = tid & 31;
    const int bx = blockIdx.x;           // 0..15
    const int z = (bx >> 3);             // 0 = Q, 1 = K
    const int colBase = (bx & 7) * 128;
    const int mw = (warp & 1) * 32;
    const int nw = (warp >> 1) * 32;

    if (tid < 64)
        rlTile[tid] = (mBase + tid < cnt) ? g_rowlist[mBase + tid] : 0;
    __syncthreads();

    float c[2][4][4];
    #pragma unroll
    for (int i = 0; i < 2; i++)
        #pragma unroll
        for (int j = 0; j < 4; j++)
            #pragma unroll
            for (int r = 0; r < 4; r++) c[i][j][r] = 0.f;

    const __nv_bfloat16* __restrict__ Wbase = g_W + (size_t)z * 1048576 + colBase;

    auto issue = [&](int kb) {
        const int stage = kb & (NSTAGE - 1);
        const uint32_t sA = base + (uint32_t)stage * STAGE_BYTES;
        const uint32_t sB = sA + A_BYTES;
        const int k0 = kb * BK;
        // A: 64 rows x 8 chunks = 512 -> 2/thread
        #pragma unroll
        for (int i = 0; i < 2; i++) {
            const int idx = i * 256 + tid;
            const int row = idx >> 3, ch = idx & 7;
            const __nv_bfloat16* gA = g_A + (size_t)rlTile[row] * 1024 + k0 + ch * 8;
            asm volatile("cp.async.cg.shared.global [%0], [%1], 16;"
                :: "r"(sA + (uint32_t)(row * 128 + ((ch ^ (row & 7)) << 4))), "l"(gA));
        }
        // B: 64 k-rows x 16 chunks = 1024 -> 4/thread
        #pragma unroll
        for (int i = 0; i < 4; i++) {
            const int idx = i * 256 + tid;
            const int row = idx >> 4, ch = idx & 15;
            const __nv_bfloat16* gB = Wbase + (size_t)(k0 + row) * 1024 + ch * 8;
            asm volatile("cp.async.cg.shared.global [%0], [%1], 16;"
                :: "r"(sB + (uint32_t)(row * 256 + ((ch ^ (row & 7)) << 4))), "l"(gB));
        }
        asm volatile("cp.async.commit_group;");
    };

    const int lj = lane >> 3;
    const int li = lane & 7;
    auto compute = [&](int stage) {
        const uint32_t sA = base + (uint32_t)stage * STAGE_BYTES;
        const uint32_t sB = sA + A_BYTES;
        #pragma unroll
        for (int kc = 0; kc < BK / 16; kc++) {
            uint32_t a[2][4];
            #pragma unroll
            for (int mt = 0; mt < 2; mt++) {
                const int row = mw + mt * 16 + ((lj & 1) << 3) + li;
                const int ch = kc * 2 + (lj >> 1);
                const uint32_t addr =
                    sA + (uint32_t)(row * 128 + ((ch ^ (row & 7)) << 4));
                asm volatile("ldmatrix.sync.aligned.m8n8.x4.shared.b16 "
                             "{%0,%1,%2,%3}, [%4];"
                             : "=r"(a[mt][0]), "=r"(a[mt][1]),
                               "=r"(a[mt][2]), "=r"(a[mt][3])
                             : "r"(addr));
            }
            uint32_t b[2][4];
            #pragma unroll
            for (int nh = 0; nh < 2; nh++) {
                const int krow = kc * 16 + ((lj & 1) << 3) + li;
                const int nchunk = (nw >> 3) + nh * 2 + (lj >> 1);
                const uint32_t addr =
                    sB + (uint32_t)(krow * 256 + ((nchunk ^ (krow & 7)) << 4));
                asm volatile("ldmatrix.sync.aligned.m8n8.x4.trans.shared.b16 "
                             "{%0,%1,%2,%3}, [%4];"
                             : "=r"(b[nh][0]), "=r"(b[nh][1]),
                               "=r"(b[nh][2]), "=r"(b[nh][3])
                             : "r"(addr));
            }
            #pragma unroll
            for (int mt = 0; mt < 2; mt++)
                #pragma unroll
                for (int nt = 0; nt < 4; nt++) {
                    const uint32_t b0 = b[nt >> 1][(nt & 1) * 2 + 0];
                    const uint32_t b1 = b[nt >> 1][(nt & 1) * 2 + 1];
                    asm volatile(
                        "mma.sync.aligned.m16n8k16.row.col.f32.bf16.bf16.f32 "
                        "{%0,%1,%2,%3}, {%4,%5,%6,%7}, {%8,%9}, {%0,%1,%2,%3};"
                        : "+f"(c[mt][nt][0]), "+f"(c[mt][nt][1]),
                          "+f"(c[mt][nt][2]), "+f"(c[mt][nt][3])
                        : "r"(a[mt][0]), "r"(a[mt][1]),
                          "r"(a[mt][2]), "r"(a[mt][3]),
                          "r"(b0), "r"(b1));
                }
        }
    };

    issue(0); issue(1); issue(2);
    for (int kb = 0; kb < 16; kb++) {
        if (kb <= 13)      asm volatile("cp.async.wait_group 2;");
        else if (kb == 14) asm volatile("cp.async.wait_group 1;");
        else               asm volatile("cp.async.wait_group 0;");
        __syncthreads();
        if (kb + 3 < 16) issue(kb + 3);
        compute(kb & (NSTAGE - 1));
    }

    // epilogue: bias, scatter to original rows
    const float* __restrict__ bias = z ? bk : bq;
    #pragma unroll
    for (int mt = 0; mt < 2; mt++) {
        #pragma unroll
        for (int half = 0; half < 2; half++) {
            const int compact = mBase + mw + mt * 16 + (lane >> 2) + half * 8;
            if (compact >= cnt) continue;
            const int orig = rlTile[compact - mBase];
            #pragma unroll
            for (int nt = 0; nt < 4; nt++) {
                const int colL = colBase + nw + nt * 8 + (lane & 3) * 2;
                float2 v;
                v.x = c[mt][nt][half * 2 + 0] + bias[colL + 0];
                v.y = c[mt][nt][half * 2 + 1] + bias[colL + 1];
                *reinterpret_cast<float2*>(
                    g_qk + (size_t)orig * 2048 + z * 1024 + colL) = v;
            }
        }
    }
}

// ---------------- epi: partials + last-block softmax ----------------
__global__ __launch_bounds__(256) void epi(const int* __restrict__ mask,
                                           float* __restrict__ out) {
    const int ds = blockIdx.x;
    const int b  = blockIdx.y;
    const int tid = threadIdx.x, warp = tid >> 5, lane = tid & 31;
    __shared__ float ks[128];
    __shared__ float sm_m[32];
    __shared__ int isLast;

    const float* __restrict__ base = g_qk + (size_t)b * 32 * 2048;
    const int d0 = ds * 128;

    if (tid < 32) sm_m[tid] = (float)mask[b * 32 + tid];
    __syncthreads();

    if (tid < 128) {
        float s = 0.f;
        #pragma unroll
        for (int a = 0; a < 32; a++)
            s += sm_m[a] * base[a * 2048 + 1024 + d0 + tid];
        ks[tid] = s;
    }
    __syncthreads();

    #pragma unroll
    for (int xi = 0; xi < 4; xi++) {
        const int x = warp + xi * 8;
        if (sm_m[x] == 0.f) {
            if (lane == 0) g_part[(b * 32 + x) * 8 + ds] = 0.f;
            continue;
        }
        const float* __restrict__ q = base + (size_t)x * 2048 + d0;
        const float* __restrict__ k = q + 1024;
        const int d = lane * 4;
        const float4 qv = *reinterpret_cast<const float4*>(q + d);
        const float4 kv = *reinterpret_cast<const float4*>(k + d);
        const float4 sv = *reinterpret_cast<const float4*>(ks + d);
        float acc = qv.x * (sv.x - kv.x);
        acc = fmaf(qv.y, sv.y - kv.y, acc);
        acc = fmaf(qv.z, sv.z - kv.z, acc);
        acc = fmaf(qv.w, sv.w - kv.w, acc);
        #pragma unroll
        for (int o = 16; o > 0; o >>= 1)
            acc += __shfl_xor_sync(0xFFFFFFFFu, acc, o);
        if (lane == 0) g_part[(b * 32 + x) * 8 + ds] = acc;
    }

    __syncthreads();
    if (tid == 0) {
        __threadfence();
        isLast = (atomicAdd(&g_ctr, 1) == 255);
    }
    __syncthreads();
    if (!isLast) return;
    if (tid == 0) g_ctr = 0;
    __threadfence();

    #pragma unroll
    for (int p = 0; p < 4; p++) {
        const int b2 = p * 8 + warp;
        float s = 0.f;
        #pragma unroll
        for (int d = 0; d < 8; d++)
            s += g_part[(b2 * 32 + lane) * 8 + d];
        const float m = (float)mask[b2 * 32 + lane];
        float v = (m != 0.f) ? s : -100000.0f;
        float mx = v;
        #pragma unroll
        for (int o = 16; o > 0; o >>= 1)
            mx = fmaxf(mx, __shfl_xor_sync(0xFFFFFFFFu, mx, o));
        const float e = expf(v - mx);
        float sum = e;
        #pragma unroll
        for (int o = 16; o > 0; o >>= 1)
            sum += __shfl_xor_sync(0xFFFFFFFFu, sum, o);
        out[b2 * 32 + lane] = e / sum;
    }
}

extern "C" void kernel_launch(void* const* d_in, const int* in_sizes, int n_in,
                              void* d_out, int out_size) {
    const float* enc  = (const float*)d_in[0];
    const int*   mask = (const int*)  d_in[1];
    const float* wq   = (const float*)d_in[2];
    const float* bq   = (const float*)d_in[3];
    const float* wk   = (const float*)d_in[4];
    const float* bk   = (const float*)d_in[5];
    float* out = (float*)d_out;

    cudaFuncSetAttribute(qk_mma_sync,
                         cudaFuncAttributeMaxDynamicSharedMemorySize,
                         NSTAGE * STAGE_BYTES);

    convert_all<<<512, 256>>>(enc, wq, wk, mask);
    qk_mma_sync<<<dim3(16, 16), 256, NSTAGE * STAGE_BYTES>>>(bq, bk);
    epi<<<dim3(8, 32), 256>>>(mask, out);
}

// round 8
// speedup vs baseline: 1.1405x; 1.0719x over previous
#include <cuda_runtime.h>
#include <cuda_bf16.h>
#include <cstdint>
#include <math.h>

// ============================================================
// DocAttention on GB300 (sm_103 family-safe: mma.sync bf16).
//   logits[b,x] = Q[b,x]·(Σ_a K[b,a]) − Q[b,x]·K[b,x]
//   Q = (cls@Wq + bq)*m, K = (cls@Wk + bk)*m
//   out = softmax(logits + (1−m)·−1e5)
// R4 GEMM datapath (W transposed, non-trans ldmatrix, 128x128 tiles)
// + masked-row compaction + split-K=2. Bias applied in epi.
// ============================================================

__device__ __forceinline__ uint32_t smem_u32(const void* p) {
    uint32_t a;
    asm("{ .reg .u64 t; cvta.to.shared.u64 t, %1; cvt.u32.u64 %0, t; }"
        : "=r"(a) : "l"(p));
    return a;
}

// ---------------- scratch (device globals; no allocation) ----------------
__device__ __align__(16) __nv_bfloat16 g_A[1024 * 1024];     // cls bf16 [m][k]
__device__ __align__(16) __nv_bfloat16 g_B[2048 * 1024];     // [WqT|WkT] bf16 [n][k]
__device__ float g_qkA[1024 * 2048];                          // split 0 raw products
__device__ float g_qkB[1024 * 2048];                          // split 1 raw products
__device__ float g_part[1024 * 8];                            // partial logits
__device__ int   g_rowlist[1024];
__device__ int   g_rowcnt;
__device__ int   g_ctr;

// ---------------- converts + transpose + compaction ----------------
// blocks [0,128):   cls rows -> bf16 (8 rows/block, MLP=8)
// blocks [128,384): W transpose 32k x 256n tiles -> g_B [n][k]
// block 384:        mask compaction
__global__ __launch_bounds__(256) void convert_all(const float* __restrict__ enc,
                                                   const float* __restrict__ wq,
                                                   const float* __restrict__ wk,
                                                   const int*   __restrict__ mask) {
    const int blk = blockIdx.x;
    const int tid = threadIdx.x;

    if (blk < 128) {
        const int row = blk * 8 + (tid >> 5);
        const int lane = tid & 31;
        const float4* __restrict__ src =
            reinterpret_cast<const float4*>(enc + (size_t)row * 131072);
        uint2* __restrict__ dst = reinterpret_cast<uint2*>(g_A + (size_t)row * 1024);
        float4 v[8];
        #pragma unroll
        for (int i = 0; i < 8; i++) v[i] = src[lane + 32 * i];
        #pragma unroll
        for (int i = 0; i < 8; i++) {
            __nv_bfloat16 h[4];
            h[0] = __float2bfloat16(v[i].x);
            h[1] = __float2bfloat16(v[i].y);
            h[2] = __float2bfloat16(v[i].z);
            h[3] = __float2bfloat16(v[i].w);
            dst[lane + 32 * i] = *reinterpret_cast<uint2*>(h);
        }
        return;
    }

    if (blk < 384) {
        // W transpose: widx -> (z, ktile, ntile); tile = 32 k x 256 n
        __shared__ float ts[32][257];
        const int widx = blk - 128;             // 0..255
        const int z = widx >> 7;                // 0 = wq, 1 = wk
        const int rest = widx & 127;
        const int kt = rest & 31;               // 32 k-tiles
        const int nt = rest >> 5;               // 4 n-tiles
        const int k0 = kt * 32, n0 = nt * 256;
        const float* __restrict__ W = z ? wk : wq;

        const int kk = tid >> 6;                // 0..3
        const int n4 = (tid & 63) * 4;
        #pragma unroll
        for (int i = 0; i < 8; i++) {
            const int k = kk + i * 4;           // 0..31
            const float4 v = *reinterpret_cast<const float4*>(
                W + (size_t)(k0 + k) * 1024 + n0 + n4);
            ts[k][n4 + 0] = v.x;
            ts[k][n4 + 1] = v.y;
            ts[k][n4 + 2] = v.z;
            ts[k][n4 + 3] = v.w;
        }
        __syncthreads();

        __nv_bfloat16 h[32];
        #pragma unroll
        for (int k = 0; k < 32; k++)
            h[k] = __float2bfloat16(ts[k][tid]);
        uint4* __restrict__ dst = reinterpret_cast<uint4*>(
            g_B + (size_t)(z * 1024 + n0 + tid) * 1024 + k0);
        #pragma unroll
        for (int i = 0; i < 4; i++)
            dst[i] = reinterpret_cast<uint4*>(h)[i];
        return;
    }

    // compaction: warp 0
    if (tid < 32) {
        int prev = 0;
        #pragma unroll
        for (int it = 0; it < 32; it++) {
            const int idx = it * 32 + tid;
            const bool v = (mask[idx] != 0);
            const unsigned ball = __ballot_sync(0xFFFFFFFFu, v);
            if (v) g_rowlist[prev + __popc(ball & ((1u << tid) - 1u))] = idx;
            prev += __popc(ball);
        }
        if (tid == 0) g_rowcnt = prev;
    }
}

// ---------------- mma.sync GEMM (R4 datapath + compaction + splitK) --------
// CTA: 128x128 tile, 256 threads = 8 warps 2(M) x 4(N); warp tile 64x32.
// grid (16, 16): bx = col tile over 2048; by = mtile(0..7) | split<<3.
// Each split covers 8 K-chunks of 64 (K = 512). Raw products, no bias.
#define BK 64
#define STAGE_BYTES 32768
#define NSTAGE 4

__global__ __launch_bounds__(256, 1)
void qk_mma_sync() {
    const int cnt = g_rowcnt;
    const int mtile = blockIdx.y & 7;
    const int split = blockIdx.y >> 3;
    const int mBase = mtile * 128;
    if (mBase >= cnt) return;

    extern __shared__ __align__(1024) char smem[];
    __shared__ int rlTile[128];
    const uint32_t base = smem_u32(smem);
    const int tid = threadIdx.x;
    const int warp = tid >> 5, lane = tid & 31;
    const int nBase = blockIdx.x * 128;     // 0..2047
    const int mw = (warp & 1) * 64;
    const int nw = (warp >> 1) * 32;
    const int kOff = split * 8;             // chunk offset

    if (tid < 128)
        rlTile[tid] = (mBase + tid < cnt) ? g_rowlist[mBase + tid] : 0;
    __syncthreads();

    float c[4][4][4];
    #pragma unroll
    for (int i = 0; i < 4; i++)
        #pragma unroll
        for (int j = 0; j < 4; j++)
            #pragma unroll
            for (int r = 0; r < 4; r++) c[i][j][r] = 0.f;

    auto issue = [&](int kb) {
        const int stage = kb & (NSTAGE - 1);
        const uint32_t sA = base + (uint32_t)stage * STAGE_BYTES;
        const uint32_t sB = sA + 16384;
        const int k0 = (kOff + kb) * BK;
        #pragma unroll
        for (int i = 0; i < 4; i++) {
            const int idx = i * 256 + tid;
            const int row = idx >> 3, ch = idx & 7;
            const uint32_t swz = (uint32_t)((ch ^ (row & 7)) << 4);
            const __nv_bfloat16* gA =
                g_A + (size_t)rlTile[row] * 1024 + k0 + ch * 8;
            const __nv_bfloat16* gB =
                g_B + (size_t)(nBase + row) * 1024 + k0 + ch * 8;
            asm volatile("cp.async.cg.shared.global [%0], [%1], 16;"
                         :: "r"(sA + (uint32_t)row * 128 + swz), "l"(gA));
            asm volatile("cp.async.cg.shared.global [%0], [%1], 16;"
                         :: "r"(sB + (uint32_t)row * 128 + swz), "l"(gB));
        }
        asm volatile("cp.async.commit_group;");
    };

    const int lj = lane >> 3;
    const int li = lane & 7;
    auto compute = [&](int stage) {
        const uint32_t sA = base + (uint32_t)stage * STAGE_BYTES;
        const uint32_t sB = sA + 16384;
        #pragma unroll
        for (int kc = 0; kc < BK / 16; kc++) {
            uint32_t a[4][4];
            #pragma unroll
            for (int mt = 0; mt < 4; mt++) {
                const int row = mw + mt * 16 + ((lj & 1) << 3) + li;
                const int ch = kc * 2 + (lj >> 1);
                const uint32_t addr =
                    sA + (uint32_t)(row * 128 + ((ch ^ (row & 7)) << 4));
                asm volatile("ldmatrix.sync.aligned.m8n8.x4.shared.b16 "
                             "{%0,%1,%2,%3}, [%4];"
                             : "=r"(a[mt][0]), "=r"(a[mt][1]),
                               "=r"(a[mt][2]), "=r"(a[mt][3])
                             : "r"(addr));
            }
            uint32_t b[2][4];
            #pragma unroll
            for (int nh = 0; nh < 2; nh++) {
                const int row = nw + nh * 16 + ((lj >> 1) << 3) + li;
                const int ch = kc * 2 + (lj & 1);
                const uint32_t addr =
                    sB + (uint32_t)(row * 128 + ((ch ^ (row & 7)) << 4));
                asm volatile("ldmatrix.sync.aligned.m8n8.x4.shared.b16 "
                             "{%0,%1,%2,%3}, [%4];"
                             : "=r"(b[nh][0]), "=r"(b[nh][1]),
                               "=r"(b[nh][2]), "=r"(b[nh][3])
                             : "r"(addr));
            }
            #pragma unroll
            for (int mt = 0; mt < 4; mt++)
                #pragma unroll
                for (int nt = 0; nt < 4; nt++) {
                    const uint32_t b0 = b[nt >> 1][(nt & 1) * 2 + 0];
                    const uint32_t b1 = b[nt >> 1][(nt & 1) * 2 + 1];
                    asm volatile(
                        "mma.sync.aligned.m16n8k16.row.col.f32.bf16.bf16.f32 "
                        "{%0,%1,%2,%3}, {%4,%5,%6,%7}, {%8,%9}, {%0,%1,%2,%3};"
                        : "+f"(c[mt][nt][0]), "+f"(c[mt][nt][1]),
                          "+f"(c[mt][nt][2]), "+f"(c[mt][nt][3])
                        : "r"(a[mt][0]), "r"(a[mt][1]),
                          "r"(a[mt][2]), "r"(a[mt][3]),
                          "r"(b0), "r"(b1));
                }
        }
    };

    issue(0); issue(1); issue(2);
    for (int kb = 0; kb < 8; kb++) {
        if (kb <= 5)      asm volatile("cp.async.wait_group 2;");
        else if (kb == 6) asm volatile("cp.async.wait_group 1;");
        else              asm volatile("cp.async.wait_group 0;");
        __syncthreads();
        if (kb + 3 < 8) issue(kb + 3);
        compute(kb & (NSTAGE - 1));
    }

    // raw scatter to original rows; bias/mask handled in epi
    float* __restrict__ dst = split ? g_qkB : g_qkA;
    #pragma unroll
    for (int mt = 0; mt < 4; mt++) {
        #pragma unroll
        for (int half = 0; half < 2; half++) {
            const int compact = mBase + mw + mt * 16 + (lane >> 2) + half * 8;
            if (compact >= cnt) continue;
            const int orig = rlTile[compact - mBase];
            #pragma unroll
            for (int nt = 0; nt < 4; nt++) {
                const int col = nBase + nw + nt * 8 + (lane & 3) * 2;
                float2 v;
                v.x = c[mt][nt][half * 2 + 0];
                v.y = c[mt][nt][half * 2 + 1];
                *reinterpret_cast<float2*>(dst + (size_t)orig * 2048 + col) = v;
            }
        }
    }
}

// ---------------- epi: sum splits + bias, partials, last-block softmax ------
__global__ __launch_bounds__(256) void epi(const int* __restrict__ mask,
                                           const float* __restrict__ bq,
                                           const float* __restrict__ bk,
                                           float* __restrict__ out) {
    const int ds = blockIdx.x;
    const int b  = blockIdx.y;
    const int tid = threadIdx.x, warp = tid >> 5, lane = tid & 31;
    __shared__ float ks[128];
    __shared__ float sm_m[32];
    __shared__ int isLast;

    const float* __restrict__ p0 = g_qkA + (size_t)b * 32 * 2048;
    const float* __restrict__ p1 = g_qkB + (size_t)b * 32 * 2048;
    const int d0 = ds * 128;

    if (tid < 32) sm_m[tid] = (float)mask[b * 32 + tid];
    __syncthreads();

    if (tid < 128) {
        const int d = d0 + tid;
        const float bkd = bk[d];
        float s = 0.f;
        #pragma unroll
        for (int a = 0; a < 32; a++) {
            const float kv = p0[a * 2048 + 1024 + d] + p1[a * 2048 + 1024 + d] + bkd;
            s += sm_m[a] * kv;
        }
        ks[tid] = s;
    }
    __syncthreads();

    const int d = d0 + lane * 4;
    const float4 bqv = *reinterpret_cast<const float4*>(bq + d);
    const float4 bkv = *reinterpret_cast<const float4*>(bk + d);
    const float4 sv = *reinterpret_cast<const float4*>(ks + lane * 4);

    #pragma unroll
    for (int xi = 0; xi < 4; xi++) {
        const int x = warp + xi * 8;
        if (sm_m[x] == 0.f) {
            if (lane == 0) g_part[(b * 32 + x) * 8 + ds] = 0.f;
            continue;
        }
        const float4 qA = *reinterpret_cast<const float4*>(p0 + (size_t)x * 2048 + d);
        const float4 qB = *reinterpret_cast<const float4*>(p1 + (size_t)x * 2048 + d);
        const float4 kA = *reinterpret_cast<const float4*>(p0 + (size_t)x * 2048 + 1024 + d);
        const float4 kB = *reinterpret_cast<const float4*>(p1 + (size_t)x * 2048 + 1024 + d);
        float acc;
        {
            const float q0 = qA.x + qB.x + bqv.x;
            const float k0v = kA.x + kB.x + bkv.x;
            acc = q0 * (sv.x - k0v);
        }
        {
            const float q1 = qA.y + qB.y + bqv.y;
            const float k1v = kA.y + kB.y + bkv.y;
            acc = fmaf(q1, sv.y - k1v, acc);
        }
        {
            const float q2 = qA.z + qB.z + bqv.z;
            const float k2v = kA.z + kB.z + bkv.z;
            acc = fmaf(q2, sv.z - k2v, acc);
        }
        {
            const float q3 = qA.w + qB.w + bqv.w;
            const float k3v = kA.w + kB.w + bkv.w;
            acc = fmaf(q3, sv.w - k3v, acc);
        }
        #pragma unroll
        for (int o = 16; o > 0; o >>= 1)
            acc += __shfl_xor_sync(0xFFFFFFFFu, acc, o);
        if (lane == 0) g_part[(b * 32 + x) * 8 + ds] = acc;
    }

    __syncthreads();
    if (tid == 0) {
        __threadfence();
        isLast = (atomicAdd(&g_ctr, 1) == 255);
    }
    __syncthreads();
    if (!isLast) return;
    if (tid == 0) g_ctr = 0;
    __threadfence();

    #pragma unroll
    for (int p = 0; p < 4; p++) {
        const int b2 = p * 8 + warp;
        float s = 0.f;
        #pragma unroll
        for (int dd = 0; dd < 8; dd++)
            s += g_part[(b2 * 32 + lane) * 8 + dd];
        const float m = (float)mask[b2 * 32 + lane];
        float v = (m != 0.f) ? s : -100000.0f;
        float mx = v;
        #pragma unroll
        for (int o = 16; o > 0; o >>= 1)
            mx = fmaxf(mx, __shfl_xor_sync(0xFFFFFFFFu, mx, o));
        const float e = expf(v - mx);
        float sum = e;
        #pragma unroll
        for (int o = 16; o > 0; o >>= 1)
            sum += __shfl_xor_sync(0xFFFFFFFFu, sum, o);
        out[b2 * 32 + lane] = e / sum;
    }
}

extern "C" void kernel_launch(void* const* d_in, const int* in_sizes, int n_in,
                              void* d_out, int out_size) {
    const float* enc  = (const float*)d_in[0];
    const int*   mask = (const int*)  d_in[1];
    const float* wq   = (const float*)d_in[2];
    const float* bq   = (const float*)d_in[3];
    const float* wk   = (const float*)d_in[4];
    const float* bk   = (const float*)d_in[5];
    float* out = (float*)d_out;

    cudaFuncSetAttribute(qk_mma_sync,
                         cudaFuncAttributeMaxDynamicSharedMemorySize,
                         NSTAGE * STAGE_BYTES);

    convert_all<<<385, 256>>>(enc, wq, wk, mask);
    qk_mma_sync<<<dim3(16, 16), 256, NSTAGE * STAGE_BYTES>>>();
    epi<<<dim3(8, 32), 256>>>(mask, bq, bk, out);
}